// round 6
// baseline (speedup 1.0000x reference)
#include <cuda_runtime.h>
#include <cstdint>

// OctVolSynth: fused LUT-gather + elementwise synth (at LTS/HBM roofline)
//   vessels = lut[label] * texture ; (==0 -> 1) ; volume = parenchyma * vessels
//   mask = (label != 0)
//
// Traffic = 768 MB read + 512 MB write = 1.25 GB (algorithmic floor).
// Sweep so far: best = 1 vec/thread, default loads, .cs stores (~185.2us,
// DRAM 88%). This round: 256-bit (v8.f32) loads/stores — sm_100a+ feature —
// halving L1tex wavefronts per byte.

#define N_LABELS 256

__device__ __forceinline__ void ldg256_f32(const float* __restrict__ p, float r[8])
{
    asm volatile("ld.global.v8.f32 {%0,%1,%2,%3,%4,%5,%6,%7}, [%8];"
        : "=f"(r[0]), "=f"(r[1]), "=f"(r[2]), "=f"(r[3]),
          "=f"(r[4]), "=f"(r[5]), "=f"(r[6]), "=f"(r[7])
        : "l"(p));
}

__device__ __forceinline__ void ldg256_s32(const int* __restrict__ p, int r[8])
{
    asm volatile("ld.global.v8.b32 {%0,%1,%2,%3,%4,%5,%6,%7}, [%8];"
        : "=r"(r[0]), "=r"(r[1]), "=r"(r[2]), "=r"(r[3]),
          "=r"(r[4]), "=r"(r[5]), "=r"(r[6]), "=r"(r[7])
        : "l"(p));
}

__device__ __forceinline__ void stg256_cs_f32(float* __restrict__ p, const float r[8])
{
    asm volatile("st.global.cs.v8.f32 [%8], {%0,%1,%2,%3,%4,%5,%6,%7};"
        :: "f"(r[0]), "f"(r[1]), "f"(r[2]), "f"(r[3]),
           "f"(r[4]), "f"(r[5]), "f"(r[6]), "f"(r[7]),
           "l"(p)
        : "memory");
}

// Each thread handles 8 consecutive elements (one 32B chunk per stream).
// Exact grid: n/8 = 8,388,608 threads = 16384 blocks * 512. No tail.
__global__ __launch_bounds__(512)
void octvolsynth_kernel(const int* __restrict__ labels,
                        const float* __restrict__ par,
                        const float* __restrict__ tex,
                        const float* __restrict__ lut,
                        float* __restrict__ out_vol,
                        float* __restrict__ out_mask,
                        int write_mask)
{
    __shared__ float slut[N_LABELS];
    if ((threadIdx.x & 511) < N_LABELS) slut[threadIdx.x & 255] = lut[threadIdx.x & 255];
    __syncthreads();

    long base = ((long)blockIdx.x * blockDim.x + threadIdx.x) * 8;

    int   lb[8];
    float p[8], t[8];
    ldg256_s32(labels + base, lb);
    ldg256_f32(par + base, p);
    ldg256_f32(tex + base, t);

    float o[8];
#pragma unroll
    for (int k = 0; k < 8; k++) {
        float v = slut[lb[k]] * t[k];
        v = (v == 0.0f) ? 1.0f : v;
        o[k] = p[k] * v;
    }
    stg256_cs_f32(out_vol + base, o);

    if (write_mask) {
        float m[8];
#pragma unroll
        for (int k = 0; k < 8; k++) m[k] = lb[k] ? 1.0f : 0.0f;
        stg256_cs_f32(out_mask + base, m);
    }
}

extern "C" void kernel_launch(void* const* d_in, const int* in_sizes, int n_in,
                              void* d_out, int out_size)
{
    const int*   labels = (const int*)d_in[0];
    const float* par    = (const float*)d_in[1];
    const float* tex    = (const float*)d_in[2];
    const float* lut    = (const float*)d_in[3];

    long n  = (long)in_sizes[0];     // 67,108,864
    long n8 = n / 8;                 // 8,388,608 = 16384 * 512 exactly

    float* out = (float*)d_out;
    int write_mask = ((long)out_size >= 2 * n) ? 1 : 0;

    octvolsynth_kernel<<<(unsigned)(n8 / 512), 512>>>(
        labels, par, tex, lut, out, out + n, write_mask);
}

// round 7
// speedup vs baseline: 1.0176x; 1.0176x over previous
#include <cuda_runtime.h>
#include <cstdint>

// OctVolSynth: fused LUT-gather + elementwise synth — FINAL (HW roofline)
//   vessels = lut[label] * texture ; (==0 -> 1) ; volume = parenchyma * vessels
//   mask = (label != 0)
//
// Inputs: d_in[0]=labels i32[N], d_in[1]=parenchyma f32[N],
//         d_in[2]=texture f32[N], d_in[3]=lut f32[256]
// Output: volume in out[0:N), mask in out[N:2N).
//
// Traffic = 768 MB read + 512 MB write = 1.25 GB (algorithmic floor).
// Config sweep result (6 rounds): 1x float4/thread + default-policy loads +
// .cs (evict-first) stores + block 512 is optimal: ~185us kernel @ 6.96 TB/s
// = 88% of DRAM peak, pinned at the path-independent LTS chip cap.
// Tested and rejected: .cs loads (-), 2x ILP (-), v8 256-bit access (-),
// block 256 (tie). Remaining gap to spec is R/W bus turnaround.

#define N_LABELS 256

__global__ __launch_bounds__(512)
void octvolsynth_kernel(const int4* __restrict__ labels,
                        const float4* __restrict__ par,
                        const float4* __restrict__ tex,
                        const float* __restrict__ lut,
                        float4* __restrict__ out_vol,
                        float4* __restrict__ out_mask,
                        int write_mask)
{
    __shared__ float slut[N_LABELS];
    if (threadIdx.x < N_LABELS) slut[threadIdx.x] = lut[threadIdx.x];
    __syncthreads();

    long i = (long)blockIdx.x * blockDim.x + threadIdx.x;   // exact grid, no tail

    int4   lb = labels[i];
    float4 p  = par[i];
    float4 t  = tex[i];

    float v0 = slut[lb.x] * t.x;
    float v1 = slut[lb.y] * t.y;
    float v2 = slut[lb.z] * t.z;
    float v3 = slut[lb.w] * t.w;
    v0 = (v0 == 0.0f) ? 1.0f : v0;
    v1 = (v1 == 0.0f) ? 1.0f : v1;
    v2 = (v2 == 0.0f) ? 1.0f : v2;
    v3 = (v3 == 0.0f) ? 1.0f : v3;

    float4 o;
    o.x = p.x * v0;
    o.y = p.y * v1;
    o.z = p.z * v2;
    o.w = p.w * v3;
    __stcs(out_vol + i, o);   // dead after write: evict-first

    if (write_mask) {
        float4 m;
        m.x = lb.x ? 1.0f : 0.0f;
        m.y = lb.y ? 1.0f : 0.0f;
        m.z = lb.z ? 1.0f : 0.0f;
        m.w = lb.w ? 1.0f : 0.0f;
        __stcs(out_mask + i, m);
    }
}

extern "C" void kernel_launch(void* const* d_in, const int* in_sizes, int n_in,
                              void* d_out, int out_size)
{
    const int*   labels = (const int*)d_in[0];
    const float* par    = (const float*)d_in[1];
    const float* tex    = (const float*)d_in[2];
    const float* lut    = (const float*)d_in[3];

    long n  = (long)in_sizes[0];     // 67,108,864
    long n4 = n / 4;                 // 16,777,216 = 32768 * 512 exactly

    float* out = (float*)d_out;
    int write_mask = ((long)out_size >= 2 * n) ? 1 : 0;

    octvolsynth_kernel<<<(unsigned)(n4 / 512), 512>>>(
        (const int4*)labels,
        (const float4*)par,
        (const float4*)tex,
        lut,
        (float4*)out,
        (float4*)(out + n),
        write_mask);
}